// round 15
// baseline (speedup 1.0000x reference)
#include <cuda_runtime.h>

// AggregateAttention: B=4, A=2, R=36, D=2048, N=500
//   x_wx[m,r] = x[b,r] @ wx[a,r] + wxb[a,r]          (m = b*A+a)
//   u[m,r]    = wy[r] @ x_wx[m,r]                     (wy_bias cancels in softmax)
//   logit[m,r,n] = (pool[r,n] . u[m,r]) / sqrt(D)
//   out[m,r]  = softmax(logit) @ pool[r]

#define Bq 4
#define Aq 2
#define Rq 36
#define Dq 2048
#define Nq 500
#define Mq 8    // B*A
#define Vq 288  // B*A*R
#define DSPLIT 8
#define DTILE 256   // Dq / DSPLIT

__device__ float g_xwx[Vq * Dq];   // pre-init with bias; k1 RED-accumulates
__device__ float g_u[Vq * Dq];
__device__ float g_logits[Vq * 512];

__device__ __forceinline__ void red_add_v4(float* addr, float4 v) {
    asm volatile("red.global.add.v4.f32 [%0], {%1, %2, %3, %4};"
                 :: "l"(addr), "f"(v.x), "f"(v.y), "f"(v.z), "f"(v.w)
                 : "memory");
}

// ---------------------------------------------------------------------------
// Init: g_xwx = broadcast bias; zero d_out (red targets for k3_out).
// ---------------------------------------------------------------------------
__global__ __launch_bounds__(256) void k_init(
    const float* __restrict__ wxb, float* __restrict__ out)
{
    const int idx = blockIdx.x * 256 + threadIdx.x;   // float4 index
    const int vi = idx >> 9;          // vector index m*R + r
    const int m  = vi / Rq;
    const int rr = vi - m * Rq;
    const int a  = m & 1;
    const int k4 = idx & 511;
    reinterpret_cast<float4*>(g_xwx)[idx] =
        reinterpret_cast<const float4*>(wxb)[(size_t)(a * Rq + rr) * 512 + k4];
    reinterpret_cast<float4*>(out)[idx] = make_float4(0.f, 0.f, 0.f, 0.f);
}

// ---------------------------------------------------------------------------
// K1: partial x_wx over a 256-wide d-slice, RED-accumulated into g_xwx.
// grid (2 k-tiles, R, A*DSPLIT) = 1152 blocks, block 256, 3 blocks/SM.
// ---------------------------------------------------------------------------
__global__ __launch_bounds__(256, 3) void k1_xwx(
    const float* __restrict__ x, const float* __restrict__ wx)
{
    const int r = blockIdx.y;
    const int a = blockIdx.z & (Aq - 1);
    const int s = blockIdx.z >> 1;
    const int dbase = s * DTILE;

    __shared__ float xs[Bq * DTILE];  // 4 KB
    for (int i = threadIdx.x; i < Bq * DTILE; i += 256) {
        int b = i >> 8, d = i & (DTILE - 1);
        xs[i] = x[((size_t)b * Rq + r) * Dq + dbase + d];
    }
    __syncthreads();

    const int k0 = blockIdx.x * 1024 + threadIdx.x * 4;
    const float4* wp =
        reinterpret_cast<const float4*>(wx + ((size_t)(a * Rq + r)) * Dq * Dq)
        + (k0 >> 2) + (size_t)dbase * (Dq / 4);

    float4 acc[Bq];
    #pragma unroll
    for (int b = 0; b < Bq; b++) acc[b] = make_float4(0.f, 0.f, 0.f, 0.f);

    float4 wa[4], wb[4];
    #pragma unroll
    for (int j = 0; j < 4; j++)
        wa[j] = wp[(size_t)j * (Dq / 4)];

    #pragma unroll 1
    for (int d = 0; d < DTILE; d += 8) {
        #pragma unroll
        for (int j = 0; j < 4; j++)
            wb[j] = wp[(size_t)(d + 4 + j) * (Dq / 4)];
        #pragma unroll
        for (int j = 0; j < 4; j++) {
            #pragma unroll
            for (int b = 0; b < Bq; b++) {
                float xv = xs[b * DTILE + d + j];
                acc[b].x = fmaf(xv, wa[j].x, acc[b].x);
                acc[b].y = fmaf(xv, wa[j].y, acc[b].y);
                acc[b].z = fmaf(xv, wa[j].z, acc[b].z);
                acc[b].w = fmaf(xv, wa[j].w, acc[b].w);
            }
        }
        const int dn = (d + 8 < DTILE) ? d + 8 : d + 4;
        #pragma unroll
        for (int j = 0; j < 4; j++)
            wa[j] = wp[(size_t)(dn + j) * (Dq / 4)];
        #pragma unroll
        for (int j = 0; j < 4; j++) {
            #pragma unroll
            for (int b = 0; b < Bq; b++) {
                float xv = xs[b * DTILE + d + 4 + j];
                acc[b].x = fmaf(xv, wb[j].x, acc[b].x);
                acc[b].y = fmaf(xv, wb[j].y, acc[b].y);
                acc[b].z = fmaf(xv, wb[j].z, acc[b].z);
                acc[b].w = fmaf(xv, wb[j].w, acc[b].w);
            }
        }
    }

    #pragma unroll
    for (int b = 0; b < Bq; b++) {
        int m = b * Aq + a;
        red_add_v4(&g_xwx[((size_t)(m * Rq + r)) * Dq + k0], acc[b]);
    }
}

// ---------------------------------------------------------------------------
// K2: u[m*R+r][d] = sum_k wy[r,d,k] * x_wx[m*R+r][k]   (R5 version — best)
// grid (64, R), block 256, 3 blocks/SM. Even/odd double buffer.
// ---------------------------------------------------------------------------
__global__ __launch_bounds__(256, 3) void k2_u(const float* __restrict__ wy)
{
    __shared__ float xs[Mq * 1024];  // 32 KB
    const int r = blockIdx.y;
    const int warp = threadIdx.x >> 5, lane = threadIdx.x & 31;
    const int d0 = blockIdx.x * 32 + warp * 4;
    const float4* wyp = reinterpret_cast<const float4*>(wy + (size_t)r * Dq * Dq);
    float4* xs4 = reinterpret_cast<float4*>(xs);

    float acc[4][Mq];
    #pragma unroll
    for (int i = 0; i < 4; i++)
        #pragma unroll
        for (int m = 0; m < Mq; m++) acc[i][m] = 0.f;

    for (int kh = 0; kh < 2; kh++) {
        __syncthreads();
        const float4* gx4 = reinterpret_cast<const float4*>(g_xwx);
        for (int i = threadIdx.x; i < Mq * 256; i += 256) {
            int m = i >> 8, k4 = i & 255;
            xs4[i] = gx4[(size_t)(m * Rq + r) * 512 + kh * 256 + k4];
        }
        __syncthreads();

        const int base4 = kh * 256 + lane;
        float4 wa[4], wb[4];
        #pragma unroll
        for (int i = 0; i < 4; i++)
            wa[i] = wyp[(size_t)(d0 + i) * (Dq / 4) + base4];

        #pragma unroll
        for (int c = 0; c < 8; c += 2) {
            #pragma unroll
            for (int i = 0; i < 4; i++)
                wb[i] = wyp[(size_t)(d0 + i) * (Dq / 4) + base4 + (c + 1) * 32];
            #pragma unroll
            for (int m = 0; m < Mq; m++) {
                float4 xa = xs4[m * 256 + c * 32 + lane];
                #pragma unroll
                for (int i = 0; i < 4; i++)
                    acc[i][m] += wa[i].x * xa.x + wa[i].y * xa.y +
                                 wa[i].z * xa.z + wa[i].w * xa.w;
            }
            const int cn = (c + 2 < 8) ? c + 2 : c;   // tail: harmless reload
            #pragma unroll
            for (int i = 0; i < 4; i++)
                wa[i] = wyp[(size_t)(d0 + i) * (Dq / 4) + base4 + cn * 32];
            #pragma unroll
            for (int m = 0; m < Mq; m++) {
                float4 xb = xs4[m * 256 + (c + 1) * 32 + lane];
                #pragma unroll
                for (int i = 0; i < 4; i++)
                    acc[i][m] += wb[i].x * xb.x + wb[i].y * xb.y +
                                 wb[i].z * xb.z + wb[i].w * xb.w;
            }
        }
    }

    #pragma unroll
    for (int i = 0; i < 4; i++) {
        #pragma unroll
        for (int m = 0; m < Mq; m++) {
            float v = acc[i][m];
            v += __shfl_xor_sync(0xffffffffu, v, 16);
            v += __shfl_xor_sync(0xffffffffu, v, 8);
            v += __shfl_xor_sync(0xffffffffu, v, 4);
            v += __shfl_xor_sync(0xffffffffu, v, 2);
            v += __shfl_xor_sync(0xffffffffu, v, 1);
            if (lane == 0)
                g_u[((size_t)(m * Rq + r)) * Dq + d0 + i] = v;
        }
    }
}

// ---------------------------------------------------------------------------
// K3a: logit[m*R+r][n] = (pool[r,n] . u[m*R+r]) / sqrt(D)
// R3 per-warp shape (4 rows x 2 chunks, predicated-zero OOB) at BLOCK=128:
// 96 regs x 128 thr -> 5 blocks/SM = 20 warps/SM (vs 16 at block 256).
// grid (32, R) = 1152 blocks.
// ---------------------------------------------------------------------------
__global__ __launch_bounds__(128) void k3_logits(const float* __restrict__ pool)
{
    __shared__ float us[Mq * 1024];  // 32 KB
    const int r = blockIdx.y;
    const int warp = threadIdx.x >> 5, lane = threadIdx.x & 31;
    const int n0 = blockIdx.x * 16 + warp * 4;
    const float4* pp = reinterpret_cast<const float4*>(pool + (size_t)r * Nq * Dq);
    float4* us4 = reinterpret_cast<float4*>(us);

    float acc[4][Mq];
    #pragma unroll
    for (int i = 0; i < 4; i++)
        #pragma unroll
        for (int m = 0; m < Mq; m++) acc[i][m] = 0.f;

    for (int kh = 0; kh < 2; kh++) {
        __syncthreads();
        const float4* gu4 = reinterpret_cast<const float4*>(g_u);
        for (int i = threadIdx.x; i < Mq * 256; i += 128) {
            int m = i >> 8, k4 = i & 255;
            us4[i] = gu4[(size_t)(m * Rq + r) * 512 + kh * 256 + k4];
        }
        __syncthreads();

        #pragma unroll 1
        for (int kc = 0; kc < 1024; kc += 256) {
            const int k4a = (kc >> 2) + lane;
            const int k4b = k4a + 32;
            const int g4a = kh * 256 + k4a;
            const int g4b = g4a + 32;
            float4 w0[4], w1[4];
            #pragma unroll
            for (int i = 0; i < 4; i++) {
                int n = n0 + i;
                if (n < Nq) {
                    w0[i] = pp[(size_t)n * (Dq / 4) + g4a];
                    w1[i] = pp[(size_t)n * (Dq / 4) + g4b];
                } else {
                    w0[i] = make_float4(0.f, 0.f, 0.f, 0.f);
                    w1[i] = make_float4(0.f, 0.f, 0.f, 0.f);
                }
            }
            #pragma unroll
            for (int m = 0; m < Mq; m++) {
                float4 xa = us4[m * 256 + k4a];
                float4 xb = us4[m * 256 + k4b];
                #pragma unroll
                for (int i = 0; i < 4; i++) {
                    acc[i][m] += w0[i].x * xa.x + w0[i].y * xa.y +
                                 w0[i].z * xa.z + w0[i].w * xa.w;
                    acc[i][m] += w1[i].x * xb.x + w1[i].y * xb.y +
                                 w1[i].z * xb.z + w1[i].w * xb.w;
                }
            }
        }
    }

    const float scale = 0.022097086912079612f;  // 1/sqrt(2048)
    #pragma unroll
    for (int i = 0; i < 4; i++) {
        #pragma unroll
        for (int m = 0; m < Mq; m++) {
            float v = acc[i][m];
            v += __shfl_xor_sync(0xffffffffu, v, 16);
            v += __shfl_xor_sync(0xffffffffu, v, 8);
            v += __shfl_xor_sync(0xffffffffu, v, 4);
            v += __shfl_xor_sync(0xffffffffu, v, 2);
            v += __shfl_xor_sync(0xffffffffu, v, 1);
            if (lane == 0 && (n0 + i) < Nq)
                g_logits[((size_t)(m * Rq + r)) * 512 + n0 + i] = v * scale;
        }
    }
}

// ---------------------------------------------------------------------------
// K3c: softmax (recomputed, cheap) + out += w @ pool[r] over an n-quarter.
// Single-wave layout: grid (2 d-tiles, R, 4 n-splits) = 288 blocks @2/SM.
// Thread owns 4 d's (float4); n unrolled x8 -> 128B in flight per thread.
// r REVERSED so pool tiles cached by k3_logits hit in L2.  (R12 — best)
// ---------------------------------------------------------------------------
__global__ __launch_bounds__(256) void k3_out(
    const float* __restrict__ pool, float* __restrict__ out)
{
    __shared__ float w[Mq * Nq];  // 16 KB
    const int r = (Rq - 1) - blockIdx.y;   // reverse order for L2 reuse
    const int warp = threadIdx.x >> 5, lane = threadIdx.x & 31;

    // Softmax over full 500 logits: warp m handles vector m.
    {
        const int m = warp;
        const float* lg = &g_logits[((size_t)(m * Rq + r)) * 512];
        float vals[16];
        float mx = -1e30f;
        #pragma unroll
        for (int i = 0; i < 16; i++) {
            int n = lane + i * 32;
            vals[i] = (n < Nq) ? lg[n] : -1e30f;
            mx = fmaxf(mx, vals[i]);
        }
        #pragma unroll
        for (int o = 16; o >= 1; o >>= 1)
            mx = fmaxf(mx, __shfl_xor_sync(0xffffffffu, mx, o));
        float s = 0.f;
        #pragma unroll
        for (int i = 0; i < 16; i++) {
            int n = lane + i * 32;
            float e = (n < Nq) ? __expf(vals[i] - mx) : 0.f;
            vals[i] = e;
            s += e;
        }
        #pragma unroll
        for (int o = 16; o >= 1; o >>= 1)
            s += __shfl_xor_sync(0xffffffffu, s, o);
        float inv = 1.f / s;
        #pragma unroll
        for (int i = 0; i < 16; i++) {
            int n = lane + i * 32;
            if (n < Nq) w[m * Nq + n] = vals[i] * inv;
        }
    }
    __syncthreads();

    const int d0 = blockIdx.x * 1024 + threadIdx.x * 4;
    const int n0 = blockIdx.z * 125;
    const float4* pr =
        reinterpret_cast<const float4*>(pool + (size_t)r * Nq * Dq) + (d0 >> 2);

    float4 acc[Mq];
    #pragma unroll
    for (int m = 0; m < Mq; m++) acc[m] = make_float4(0.f, 0.f, 0.f, 0.f);

    #pragma unroll 1
    for (int n = n0; n + 8 <= n0 + 125; n += 8) {
        float4 p[8];
        #pragma unroll
        for (int j = 0; j < 8; j++)
            p[j] = pr[(size_t)(n + j) * (Dq / 4)];
        #pragma unroll
        for (int j = 0; j < 8; j++) {
            #pragma unroll
            for (int m = 0; m < Mq; m++) {
                float wv = w[m * Nq + n + j];
                acc[m].x = fmaf(wv, p[j].x, acc[m].x);
                acc[m].y = fmaf(wv, p[j].y, acc[m].y);
                acc[m].z = fmaf(wv, p[j].z, acc[m].z);
                acc[m].w = fmaf(wv, p[j].w, acc[m].w);
            }
        }
    }
    // tail (125 = 8*15 + 5)
    #pragma unroll
    for (int t = 0; t < 5; t++) {
        int n = n0 + 120 + t;
        float4 p = pr[(size_t)n * (Dq / 4)];
        #pragma unroll
        for (int m = 0; m < Mq; m++) {
            float wv = w[m * Nq + n];
            acc[m].x = fmaf(wv, p.x, acc[m].x);
            acc[m].y = fmaf(wv, p.y, acc[m].y);
            acc[m].z = fmaf(wv, p.z, acc[m].z);
            acc[m].w = fmaf(wv, p.w, acc[m].w);
        }
    }

    #pragma unroll
    for (int m = 0; m < Mq; m++)
        red_add_v4(out + ((size_t)(m * Rq + r)) * Dq + d0, acc[m]);
}

// ---------------------------------------------------------------------------
extern "C" void kernel_launch(void* const* d_in, const int* in_sizes, int n_in,
                              void* d_out, int out_size)
{
    const float* x    = (const float*)d_in[0];  // (B,R,D)
    const float* pool = (const float*)d_in[1];  // (R,N,D)
    const float* wx   = (const float*)d_in[2];  // (A,R,D,D)
    const float* wxb  = (const float*)d_in[3];  // (A,R,1,D)
    const float* wy   = (const float*)d_in[4];  // (R,D,D)
    // d_in[5] = wy_bias: cancels in softmax (constant over n).
    float* out = (float*)d_out;                 // (B,A,R,1,D)
    (void)in_sizes; (void)n_in; (void)out_size;

    k_init   <<<dim3(Vq * Dq / 1024),             256>>>(wxb, out);
    k1_xwx   <<<dim3(Dq / 1024, Rq, Aq * DSPLIT), 256>>>(x, wx);
    k2_u     <<<dim3(Dq / 32, Rq),                256>>>(wy);
    k3_logits<<<dim3(32, Rq),                     128>>>(pool);
    k3_out   <<<dim3(2, Rq, 4),                   256>>>(pool, out);
}

// round 16
// speedup vs baseline: 1.0069x; 1.0069x over previous
#include <cuda_runtime.h>

// AggregateAttention: B=4, A=2, R=36, D=2048, N=500
//   x_wx[m,r] = x[b,r] @ wx[a,r] + wxb[a,r]          (m = b*A+a)
//   u[m,r]    = wy[r] @ x_wx[m,r]                     (wy_bias cancels in softmax)
//   logit[m,r,n] = (pool[r,n] . u[m,r]) / sqrt(D)
//   out[m,r]  = softmax(logit) @ pool[r]

#define Bq 4
#define Aq 2
#define Rq 36
#define Dq 2048
#define Nq 500
#define Mq 8    // B*A
#define Vq 288  // B*A*R
#define DSPLIT 8
#define DTILE 256   // Dq / DSPLIT

__device__ float g_xwx[Vq * Dq];   // pre-init with bias; k1 RED-accumulates
__device__ float g_u[Vq * Dq];
__device__ float g_logits[Vq * 512];

__device__ __forceinline__ void red_add_v4(float* addr, float4 v) {
    asm volatile("red.global.add.v4.f32 [%0], {%1, %2, %3, %4};"
                 :: "l"(addr), "f"(v.x), "f"(v.y), "f"(v.z), "f"(v.w)
                 : "memory");
}

// ---------------------------------------------------------------------------
// Init: g_xwx = broadcast bias; zero d_out (red targets for k3_out).
// ---------------------------------------------------------------------------
__global__ __launch_bounds__(256) void k_init(
    const float* __restrict__ wxb, float* __restrict__ out)
{
    const int idx = blockIdx.x * 256 + threadIdx.x;   // float4 index
    const int vi = idx >> 9;          // vector index m*R + r
    const int m  = vi / Rq;
    const int rr = vi - m * Rq;
    const int a  = m & 1;
    const int k4 = idx & 511;
    reinterpret_cast<float4*>(g_xwx)[idx] =
        reinterpret_cast<const float4*>(wxb)[(size_t)(a * Rq + rr) * 512 + k4];
    reinterpret_cast<float4*>(out)[idx] = make_float4(0.f, 0.f, 0.f, 0.f);
}

// ---------------------------------------------------------------------------
// K1: partial x_wx over a 256-wide d-slice, RED-accumulated into g_xwx.
// grid (2 k-tiles, R, A*DSPLIT) = 1152 blocks, block 256, 3 blocks/SM.
// 3-buffer rotating pipeline, prefetch distance 2 (4-row stages):
// 8 LDG.128 in flight per warp steady-state (vs 4 in the double buffer).
// Stage loop unrolled x3 so buffer indices are static (no register moves).
// ---------------------------------------------------------------------------
__global__ __launch_bounds__(256, 3) void k1_xwx(
    const float* __restrict__ x, const float* __restrict__ wx)
{
    const int r = blockIdx.y;
    const int a = blockIdx.z & (Aq - 1);
    const int s = blockIdx.z >> 1;
    const int dbase = s * DTILE;

    __shared__ float xs[Bq * DTILE];  // 4 KB
    for (int i = threadIdx.x; i < Bq * DTILE; i += 256) {
        int b = i >> 8, d = i & (DTILE - 1);
        xs[i] = x[((size_t)b * Rq + r) * Dq + dbase + d];
    }
    __syncthreads();

    const int k0 = blockIdx.x * 1024 + threadIdx.x * 4;
    const float4* wp =
        reinterpret_cast<const float4*>(wx + ((size_t)(a * Rq + r)) * Dq * Dq)
        + (k0 >> 2) + (size_t)dbase * (Dq / 4);

    float4 acc[Bq];
    #pragma unroll
    for (int b = 0; b < Bq; b++) acc[b] = make_float4(0.f, 0.f, 0.f, 0.f);

    // 64 stages of 4 rows each. Invariant at loop top (stage s0):
    // w0 = stage s0, w1 = stage s0+1.
    float4 w0[4], w1[4], w2[4];
    #pragma unroll
    for (int j = 0; j < 4; j++) {
        w0[j] = wp[(size_t)(0 + j) * (Dq / 4)];
        w1[j] = wp[(size_t)(4 + j) * (Dq / 4)];
    }

    #define K1_COMPUTE(buf, row0)                                        \
        _Pragma("unroll")                                                 \
        for (int j = 0; j < 4; j++) {                                     \
            _Pragma("unroll")                                             \
            for (int b = 0; b < Bq; b++) {                                \
                float xv = xs[b * DTILE + (row0) + j];                    \
                acc[b].x = fmaf(xv, buf[j].x, acc[b].x);                  \
                acc[b].y = fmaf(xv, buf[j].y, acc[b].y);                  \
                acc[b].z = fmaf(xv, buf[j].z, acc[b].z);                  \
                acc[b].w = fmaf(xv, buf[j].w, acc[b].w);                  \
            }                                                             \
        }

    #pragma unroll 1
    for (int t = 0; t < 21; t++) {
        const int d0 = t * 12;   // rows of stage 3t
        // stage 3t: prefetch 3t+2, compute w0
        #pragma unroll
        for (int j = 0; j < 4; j++)
            w2[j] = wp[(size_t)(d0 + 8 + j) * (Dq / 4)];
        K1_COMPUTE(w0, d0)
        // stage 3t+1: prefetch 3t+3, compute w1
        #pragma unroll
        for (int j = 0; j < 4; j++)
            w0[j] = wp[(size_t)(d0 + 12 + j) * (Dq / 4)];
        K1_COMPUTE(w1, d0 + 4)
        // stage 3t+2: prefetch 3t+4 (clamped in-bounds on last iter), compute w2
        const int dpre = (d0 + 16 < DTILE) ? d0 + 16 : DTILE - 4;
        #pragma unroll
        for (int j = 0; j < 4; j++)
            w1[j] = wp[(size_t)(dpre + j) * (Dq / 4)];
        K1_COMPUTE(w2, d0 + 8)
    }
    // final stage 63 (rows 252..255) is in w0
    K1_COMPUTE(w0, 252)
    #undef K1_COMPUTE

    #pragma unroll
    for (int b = 0; b < Bq; b++) {
        int m = b * Aq + a;
        red_add_v4(&g_xwx[((size_t)(m * Rq + r)) * Dq + k0], acc[b]);
    }
}

// ---------------------------------------------------------------------------
// K2: u[m*R+r][d] = sum_k wy[r,d,k] * x_wx[m*R+r][k]   (R5 version — best)
// grid (64, R), block 256, 3 blocks/SM. Even/odd double buffer.
// ---------------------------------------------------------------------------
__global__ __launch_bounds__(256, 3) void k2_u(const float* __restrict__ wy)
{
    __shared__ float xs[Mq * 1024];  // 32 KB
    const int r = blockIdx.y;
    const int warp = threadIdx.x >> 5, lane = threadIdx.x & 31;
    const int d0 = blockIdx.x * 32 + warp * 4;
    const float4* wyp = reinterpret_cast<const float4*>(wy + (size_t)r * Dq * Dq);
    float4* xs4 = reinterpret_cast<float4*>(xs);

    float acc[4][Mq];
    #pragma unroll
    for (int i = 0; i < 4; i++)
        #pragma unroll
        for (int m = 0; m < Mq; m++) acc[i][m] = 0.f;

    for (int kh = 0; kh < 2; kh++) {
        __syncthreads();
        const float4* gx4 = reinterpret_cast<const float4*>(g_xwx);
        for (int i = threadIdx.x; i < Mq * 256; i += 256) {
            int m = i >> 8, k4 = i & 255;
            xs4[i] = gx4[(size_t)(m * Rq + r) * 512 + kh * 256 + k4];
        }
        __syncthreads();

        const int base4 = kh * 256 + lane;
        float4 wa[4], wb[4];
        #pragma unroll
        for (int i = 0; i < 4; i++)
            wa[i] = wyp[(size_t)(d0 + i) * (Dq / 4) + base4];

        #pragma unroll
        for (int c = 0; c < 8; c += 2) {
            #pragma unroll
            for (int i = 0; i < 4; i++)
                wb[i] = wyp[(size_t)(d0 + i) * (Dq / 4) + base4 + (c + 1) * 32];
            #pragma unroll
            for (int m = 0; m < Mq; m++) {
                float4 xa = xs4[m * 256 + c * 32 + lane];
                #pragma unroll
                for (int i = 0; i < 4; i++)
                    acc[i][m] += wa[i].x * xa.x + wa[i].y * xa.y +
                                 wa[i].z * xa.z + wa[i].w * xa.w;
            }
            const int cn = (c + 2 < 8) ? c + 2 : c;   // tail: harmless reload
            #pragma unroll
            for (int i = 0; i < 4; i++)
                wa[i] = wyp[(size_t)(d0 + i) * (Dq / 4) + base4 + cn * 32];
            #pragma unroll
            for (int m = 0; m < Mq; m++) {
                float4 xb = xs4[m * 256 + (c + 1) * 32 + lane];
                #pragma unroll
                for (int i = 0; i < 4; i++)
                    acc[i][m] += wb[i].x * xb.x + wb[i].y * xb.y +
                                 wb[i].z * xb.z + wb[i].w * xb.w;
            }
        }
    }

    #pragma unroll
    for (int i = 0; i < 4; i++) {
        #pragma unroll
        for (int m = 0; m < Mq; m++) {
            float v = acc[i][m];
            v += __shfl_xor_sync(0xffffffffu, v, 16);
            v += __shfl_xor_sync(0xffffffffu, v, 8);
            v += __shfl_xor_sync(0xffffffffu, v, 4);
            v += __shfl_xor_sync(0xffffffffu, v, 2);
            v += __shfl_xor_sync(0xffffffffu, v, 1);
            if (lane == 0)
                g_u[((size_t)(m * Rq + r)) * Dq + d0 + i] = v;
        }
    }
}

// ---------------------------------------------------------------------------
// K3a: logit[m*R+r][n] = (pool[r,n] . u[m*R+r]) / sqrt(D)
// R3/R14 body (measured best 38us): uncapped, block 256, 4 rows x 2 chunks,
// predicated-zero OOB. grid (16, R).
// ---------------------------------------------------------------------------
__global__ __launch_bounds__(256) void k3_logits(const float* __restrict__ pool)
{
    __shared__ float us[Mq * 1024];  // 32 KB
    const int r = blockIdx.y;
    const int warp = threadIdx.x >> 5, lane = threadIdx.x & 31;
    const int n0 = blockIdx.x * 32 + warp * 4;
    const float4* pp = reinterpret_cast<const float4*>(pool + (size_t)r * Nq * Dq);
    float4* us4 = reinterpret_cast<float4*>(us);

    float acc[4][Mq];
    #pragma unroll
    for (int i = 0; i < 4; i++)
        #pragma unroll
        for (int m = 0; m < Mq; m++) acc[i][m] = 0.f;

    for (int kh = 0; kh < 2; kh++) {
        __syncthreads();
        const float4* gu4 = reinterpret_cast<const float4*>(g_u);
        for (int i = threadIdx.x; i < Mq * 256; i += 256) {
            int m = i >> 8, k4 = i & 255;
            us4[i] = gu4[(size_t)(m * Rq + r) * 512 + kh * 256 + k4];
        }
        __syncthreads();

        #pragma unroll 1
        for (int kc = 0; kc < 1024; kc += 256) {
            const int k4a = (kc >> 2) + lane;
            const int k4b = k4a + 32;
            const int g4a = kh * 256 + k4a;
            const int g4b = g4a + 32;
            float4 w0[4], w1[4];
            #pragma unroll
            for (int i = 0; i < 4; i++) {
                int n = n0 + i;
                if (n < Nq) {
                    w0[i] = pp[(size_t)n * (Dq / 4) + g4a];
                    w1[i] = pp[(size_t)n * (Dq / 4) + g4b];
                } else {
                    w0[i] = make_float4(0.f, 0.f, 0.f, 0.f);
                    w1[i] = make_float4(0.f, 0.f, 0.f, 0.f);
                }
            }
            #pragma unroll
            for (int m = 0; m < Mq; m++) {
                float4 xa = us4[m * 256 + k4a];
                float4 xb = us4[m * 256 + k4b];
                #pragma unroll
                for (int i = 0; i < 4; i++) {
                    acc[i][m] += w0[i].x * xa.x + w0[i].y * xa.y +
                                 w0[i].z * xa.z + w0[i].w * xa.w;
                    acc[i][m] += w1[i].x * xb.x + w1[i].y * xb.y +
                                 w1[i].z * xb.z + w1[i].w * xb.w;
                }
            }
        }
    }

    const float scale = 0.022097086912079612f;  // 1/sqrt(2048)
    #pragma unroll
    for (int i = 0; i < 4; i++) {
        #pragma unroll
        for (int m = 0; m < Mq; m++) {
            float v = acc[i][m];
            v += __shfl_xor_sync(0xffffffffu, v, 16);
            v += __shfl_xor_sync(0xffffffffu, v, 8);
            v += __shfl_xor_sync(0xffffffffu, v, 4);
            v += __shfl_xor_sync(0xffffffffu, v, 2);
            v += __shfl_xor_sync(0xffffffffu, v, 1);
            if (lane == 0 && (n0 + i) < Nq)
                g_logits[((size_t)(m * Rq + r)) * 512 + n0 + i] = v * scale;
        }
    }
}

// ---------------------------------------------------------------------------
// K3c: softmax (recomputed, cheap) + out += w @ pool[r] over an n-quarter.
// Single-wave layout: grid (2 d-tiles, R, 4 n-splits) = 288 blocks @2/SM.
// Thread owns 4 d's (float4); n unrolled x8 -> 128B in flight per thread.
// r REVERSED so pool tiles cached by k3_logits hit in L2.  (R12 — best)
// ---------------------------------------------------------------------------
__global__ __launch_bounds__(256) void k3_out(
    const float* __restrict__ pool, float* __restrict__ out)
{
    __shared__ float w[Mq * Nq];  // 16 KB
    const int r = (Rq - 1) - blockIdx.y;   // reverse order for L2 reuse
    const int warp = threadIdx.x >> 5, lane = threadIdx.x & 31;

    // Softmax over full 500 logits: warp m handles vector m.
    {
        const int m = warp;
        const float* lg = &g_logits[((size_t)(m * Rq + r)) * 512];
        float vals[16];
        float mx = -1e30f;
        #pragma unroll
        for (int i = 0; i < 16; i++) {
            int n = lane + i * 32;
            vals[i] = (n < Nq) ? lg[n] : -1e30f;
            mx = fmaxf(mx, vals[i]);
        }
        #pragma unroll
        for (int o = 16; o >= 1; o >>= 1)
            mx = fmaxf(mx, __shfl_xor_sync(0xffffffffu, mx, o));
        float s = 0.f;
        #pragma unroll
        for (int i = 0; i < 16; i++) {
            int n = lane + i * 32;
            float e = (n < Nq) ? __expf(vals[i] - mx) : 0.f;
            vals[i] = e;
            s += e;
        }
        #pragma unroll
        for (int o = 16; o >= 1; o >>= 1)
            s += __shfl_xor_sync(0xffffffffu, s, o);
        float inv = 1.f / s;
        #pragma unroll
        for (int i = 0; i < 16; i++) {
            int n = lane + i * 32;
            if (n < Nq) w[m * Nq + n] = vals[i] * inv;
        }
    }
    __syncthreads();

    const int d0 = blockIdx.x * 1024 + threadIdx.x * 4;
    const int n0 = blockIdx.z * 125;
    const float4* pr =
        reinterpret_cast<const float4*>(pool + (size_t)r * Nq * Dq) + (d0 >> 2);

    float4 acc[Mq];
    #pragma unroll
    for (int m = 0; m < Mq; m++) acc[m] = make_float4(0.f, 0.f, 0.f, 0.f);

    #pragma unroll 1
    for (int n = n0; n + 8 <= n0 + 125; n += 8) {
        float4 p[8];
        #pragma unroll
        for (int j = 0; j < 8; j++)
            p[j] = pr[(size_t)(n + j) * (Dq / 4)];
        #pragma unroll
        for (int j = 0; j < 8; j++) {
            #pragma unroll
            for (int m = 0; m < Mq; m++) {
                float wv = w[m * Nq + n + j];
                acc[m].x = fmaf(wv, p[j].x, acc[m].x);
                acc[m].y = fmaf(wv, p[j].y, acc[m].y);
                acc[m].z = fmaf(wv, p[j].z, acc[m].z);
                acc[m].w = fmaf(wv, p[j].w, acc[m].w);
            }
        }
    }
    // tail (125 = 8*15 + 5)
    #pragma unroll
    for (int t = 0; t < 5; t++) {
        int n = n0 + 120 + t;
        float4 p = pr[(size_t)n * (Dq / 4)];
        #pragma unroll
        for (int m = 0; m < Mq; m++) {
            float wv = w[m * Nq + n];
            acc[m].x = fmaf(wv, p.x, acc[m].x);
            acc[m].y = fmaf(wv, p.y, acc[m].y);
            acc[m].z = fmaf(wv, p.z, acc[m].z);
            acc[m].w = fmaf(wv, p.w, acc[m].w);
        }
    }

    #pragma unroll
    for (int m = 0; m < Mq; m++)
        red_add_v4(out + ((size_t)(m * Rq + r)) * Dq + d0, acc[m]);
}

// ---------------------------------------------------------------------------
extern "C" void kernel_launch(void* const* d_in, const int* in_sizes, int n_in,
                              void* d_out, int out_size)
{
    const float* x    = (const float*)d_in[0];  // (B,R,D)
    const float* pool = (const float*)d_in[1];  // (R,N,D)
    const float* wx   = (const float*)d_in[2];  // (A,R,D,D)
    const float* wxb  = (const float*)d_in[3];  // (A,R,1,D)
    const float* wy   = (const float*)d_in[4];  // (R,D,D)
    // d_in[5] = wy_bias: cancels in softmax (constant over n).
    float* out = (float*)d_out;                 // (B,A,R,1,D)
    (void)in_sizes; (void)n_in; (void)out_size;

    k_init   <<<dim3(Vq * Dq / 1024),             256>>>(wxb, out);
    k1_xwx   <<<dim3(Dq / 1024, Rq, Aq * DSPLIT), 256>>>(x, wx);
    k2_u     <<<dim3(Dq / 32, Rq),                256>>>(wy);
    k3_logits<<<dim3(16, Rq),                     256>>>(pool);
    k3_out   <<<dim3(2, Rq, 4),                   256>>>(pool, out);
}